// round 1
// baseline (speedup 1.0000x reference)
#include <cuda_runtime.h>

#define NN 50000
#define NE 800000
#define IND 2613
#define HD  256

// ---------------- scratch (static device memory; no allocs) ----------------
__device__ float g_h[(size_t)NN * HD];   // GEMM output / messages (hs)
__device__ float g_x[(size_t)NN * HD];   // layer activations
__device__ float g_dinv[NN];
__device__ int   g_deg[NN];
__device__ int   g_cursor[NN];
__device__ int   g_rowptr[NN + 1];
__device__ int   g_srcs[NE];

// ---------------- CSR build ----------------
__global__ void k_zero() {
    int i = blockIdx.x * blockDim.x + threadIdx.x;
    if (i < NN) { g_deg[i] = 0; g_cursor[i] = 0; }
}

__global__ void k_histo(const int* __restrict__ dst) {
    int e = blockIdx.x * blockDim.x + threadIdx.x;
    if (e < NE) atomicAdd(&g_deg[dst[e]], 1);
}

// single-block exclusive scan over 50000 degrees; also computes dinv
__global__ void k_scan() {
    __shared__ int s[1024];
    __shared__ int carry_s;
    int tid = threadIdx.x;
    if (tid == 0) carry_s = 0;
    __syncthreads();
    for (int base = 0; base < NN; base += 1024) {
        int i = base + tid;
        int v = (i < NN) ? g_deg[i] : 0;
        if (i < NN) g_dinv[i] = rsqrtf((float)(v + 1));
        s[tid] = v;
        __syncthreads();
        #pragma unroll
        for (int off = 1; off < 1024; off <<= 1) {
            int t = (tid >= off) ? s[tid - off] : 0;
            __syncthreads();
            s[tid] += t;
            __syncthreads();
        }
        int incl  = s[tid];
        int carry = carry_s;
        if (i < NN) g_rowptr[i] = carry + incl - v;   // exclusive
        __syncthreads();
        if (tid == 1023) carry_s = carry + incl;
        __syncthreads();
    }
    if (tid == 0) g_rowptr[NN] = carry_s;
}

__global__ void k_scatter(const int* __restrict__ src, const int* __restrict__ dst) {
    int e = blockIdx.x * blockDim.x + threadIdx.x;
    if (e < NE) {
        int d = dst[e];
        int p = g_rowptr[d] + atomicAdd(&g_cursor[d], 1);
        g_srcs[p] = src[e];
    }
}

// ---------------- SGEMM: C[i,j] = sum_k A[i,k] * B[j,k]  (both K-major) ----
// EPI 0: C = acc * dinv[row]          (GCN pre-scale, bias later)
// EPI 1: C = elu(acc + bias[col])     (MLP hidden)
// EPI 2: C = acc + bias[col]          (MLP output)
template <int EPI>
__global__ void __launch_bounds__(256)
k_gemm(const float* __restrict__ A, const float* __restrict__ B,
       const float* __restrict__ bias, float* __restrict__ C,
       int M, int Nc, int K)
{
    __shared__ float As[8][128];
    __shared__ float Bs[8][128];

    const int tid = threadIdx.x;
    const int bm  = blockIdx.y * 128;
    const int bn  = blockIdx.x * 128;
    const int tx  = tid & 15;     // 16 thread-cols
    const int ty  = tid >> 4;     // 16 thread-rows
    const int lr  = tid >> 1;     // load row within tile (0..127)
    const int lk  = (tid & 1) * 4;

    float acc[8][8];
    #pragma unroll
    for (int i = 0; i < 8; i++)
        #pragma unroll
        for (int j = 0; j < 8; j++) acc[i][j] = 0.f;

    const bool avalid = (bm + lr) < M;
    const bool bvalid = (bn + lr) < Nc;
    const float* Arow = A + (size_t)(bm + lr) * K;
    const float* Brow = B + (size_t)(bn + lr) * K;

    for (int k0 = 0; k0 < K; k0 += 8) {
        #pragma unroll
        for (int i = 0; i < 4; i++) {
            int k = k0 + lk + i;
            bool kin = k < K;
            As[lk + i][lr] = (avalid && kin) ? __ldg(&Arow[k]) : 0.f;
            Bs[lk + i][lr] = (bvalid && kin) ? __ldg(&Brow[k]) : 0.f;
        }
        __syncthreads();
        #pragma unroll
        for (int kk = 0; kk < 8; kk++) {
            float4 a0 = *(const float4*)&As[kk][ty * 8];
            float4 a1 = *(const float4*)&As[kk][ty * 8 + 4];
            float4 b0 = *(const float4*)&Bs[kk][tx * 8];
            float4 b1 = *(const float4*)&Bs[kk][tx * 8 + 4];
            float a[8] = {a0.x, a0.y, a0.z, a0.w, a1.x, a1.y, a1.z, a1.w};
            float b[8] = {b0.x, b0.y, b0.z, b0.w, b1.x, b1.y, b1.z, b1.w};
            #pragma unroll
            for (int i = 0; i < 8; i++)
                #pragma unroll
                for (int j = 0; j < 8; j++)
                    acc[i][j] = fmaf(a[i], b[j], acc[i][j]);
        }
        __syncthreads();
    }

    #pragma unroll
    for (int i = 0; i < 8; i++) {
        int row = bm + ty * 8 + i;
        if (row >= M) continue;
        float dv = (EPI == 0) ? g_dinv[row] : 0.f;
        float* Crow = C + (size_t)row * Nc + bn + tx * 8;
        float o[8];
        #pragma unroll
        for (int j = 0; j < 8; j++) {
            float v = acc[i][j];
            if (EPI == 0) {
                v *= dv;
            } else {
                v += bias[bn + tx * 8 + j];
                if (EPI == 1) v = (v > 0.f) ? v : expm1f(v);
            }
            o[j] = v;
        }
        *(float4*)&Crow[0] = make_float4(o[0], o[1], o[2], o[3]);
        *(float4*)&Crow[4] = make_float4(o[4], o[5], o[6], o[7]);
    }
}

// ---------------- aggregation: one block per node ----------------
// out[v] = l2norm( relu( dinv[v] * (sum_{u->v} hs[u] + hs[v]) + bias ) )
__global__ void __launch_bounds__(HD)
k_agg(const float* __restrict__ hs, const float* __restrict__ bias,
      float* __restrict__ outx)
{
    int v = blockIdx.x;
    int j = threadIdx.x;

    float s = hs[(size_t)v * HD + j];           // self-loop term (hs includes dinv)
    int beg = g_rowptr[v], end = g_rowptr[v + 1];
    for (int e = beg; e < end; e++) {
        int u = g_srcs[e];                       // uniform across block -> broadcast
        s += hs[(size_t)u * HD + j];             // coalesced row read (L2 resident)
    }
    float val = fmaf(g_dinv[v], s, bias[j]);
    val = fmaxf(val, 0.f);

    // block reduce sum of squares (256 threads = 8 warps)
    __shared__ float red[8];
    float ss = val * val;
    #pragma unroll
    for (int o = 16; o; o >>= 1) ss += __shfl_xor_sync(0xffffffffu, ss, o);
    if ((j & 31) == 0) red[j >> 5] = ss;
    __syncthreads();
    if (j < 8) {
        float t = red[j];
        #pragma unroll
        for (int o = 4; o; o >>= 1) t += __shfl_xor_sync(0xffu, t, o);
        if (j == 0) red[0] = t;
    }
    __syncthreads();
    float scale = 1.f / fmaxf(sqrtf(red[0]), 1e-12f);
    outx[(size_t)v * HD + j] = val * scale;
}

// ---------------- launch ----------------
extern "C" void kernel_launch(void* const* d_in, const int* in_sizes, int n_in,
                              void* d_out, int out_size)
{
    const float* x     = (const float*)d_in[0];
    const int*   edges = (const int*)  d_in[1];
    const float* Wg0   = (const float*)d_in[2];
    const float* bg0   = (const float*)d_in[3];
    const float* Wg1   = (const float*)d_in[4];
    const float* bg1   = (const float*)d_in[5];
    const float* Wg2   = (const float*)d_in[6];
    const float* bg2   = (const float*)d_in[7];
    const float* W1    = (const float*)d_in[8];
    const float* b1    = (const float*)d_in[9];
    const float* W2    = (const float*)d_in[10];
    const float* b2    = (const float*)d_in[11];
    float* out = (float*)d_out;

    const int* src = edges;        // edges[0,:]
    const int* dst = edges + NE;   // edges[1,:]

    float *hp, *xp;
    cudaGetSymbolAddress((void**)&hp, g_h);
    cudaGetSymbolAddress((void**)&xp, g_x);

    // CSR build + dinv
    k_zero   <<<(NN + 255) / 256, 256>>>();
    k_histo  <<<(NE + 255) / 256, 256>>>(dst);
    k_scan   <<<1, 1024>>>();
    k_scatter<<<(NE + 255) / 256, 256>>>(src, dst);

    dim3 blk(256);
    dim3 grd(HD / 128, (NN + 127) / 128);   // (2, 391)

    // GCN layer 0 (K = 2613)
    k_gemm<0><<<grd, blk>>>(x,  Wg0, nullptr, hp, NN, HD, IND);
    k_agg    <<<NN, HD>>>(hp, bg0, xp);
    // GCN layer 1
    k_gemm<0><<<grd, blk>>>(xp, Wg1, nullptr, hp, NN, HD, HD);
    k_agg    <<<NN, HD>>>(hp, bg1, xp);
    // GCN layer 2
    k_gemm<0><<<grd, blk>>>(xp, Wg2, nullptr, hp, NN, HD, HD);
    k_agg    <<<NN, HD>>>(hp, bg2, xp);
    // MLP
    k_gemm<1><<<grd, blk>>>(xp, W1, b1, hp,  NN, HD, HD);
    k_gemm<2><<<grd, blk>>>(hp, W2, b2, out, NN, HD, HD);
}

// round 3
// speedup vs baseline: 2.3014x; 2.3014x over previous
#include <cuda_runtime.h>
#include <cstdint>

#define NN 50000
#define NE 800000
#define IND 2613
#define HD  256

// ---------------- scratch (static device memory; no allocs) ----------------
__device__ float g_h[(size_t)NN * HD];   // GEMM output / messages (hs)
__device__ float g_x[(size_t)NN * HD];   // layer activations
__device__ float g_dinv[NN];
__device__ int   g_deg[NN];
__device__ int   g_cursor[NN];
__device__ int   g_rowptr[NN + 1];
__device__ int   g_srcs[NE];

// ============================ PTX helpers ============================
__device__ __forceinline__ uint32_t smem_u32(const void* p) {
    uint32_t a;
    asm("{ .reg .u64 t; cvta.to.shared.u64 t, %1; cvt.u32.u64 %0, t; }" : "=r"(a) : "l"(p));
    return a;
}
__device__ __forceinline__ void ldmx4(uint32_t* r, uint32_t addr) {
    asm volatile("ldmatrix.sync.aligned.m8n8.x4.shared.b16 {%0,%1,%2,%3}, [%4];"
                 : "=r"(r[0]), "=r"(r[1]), "=r"(r[2]), "=r"(r[3]) : "r"(addr));
}
__device__ __forceinline__ void mma_bf16(float* c, const uint32_t* a, const uint32_t* b) {
    asm volatile("mma.sync.aligned.m16n8k16.row.col.f32.bf16.bf16.f32 "
                 "{%0,%1,%2,%3}, {%4,%5,%6,%7}, {%8,%9}, {%0,%1,%2,%3};"
                 : "+f"(c[0]), "+f"(c[1]), "+f"(c[2]), "+f"(c[3])
                 : "r"(a[0]), "r"(a[1]), "r"(a[2]), "r"(a[3]), "r"(b[0]), "r"(b[1]));
}
// 4 fp32 -> 4 bf16 hi + 4 bf16 lo (packed as uint2 each)
__device__ __forceinline__ void cvt4(const float* f, uint2& hi, uint2& lo) {
    uint32_t h0, h1, l0, l1;
    asm("cvt.rn.bf16x2.f32 %0, %1, %2;" : "=r"(h0) : "f"(f[1]), "f"(f[0]));
    asm("cvt.rn.bf16x2.f32 %0, %1, %2;" : "=r"(h1) : "f"(f[3]), "f"(f[2]));
    float r0 = f[0] - __uint_as_float(h0 << 16);
    float r1 = f[1] - __uint_as_float(h0 & 0xffff0000u);
    float r2 = f[2] - __uint_as_float(h1 << 16);
    float r3 = f[3] - __uint_as_float(h1 & 0xffff0000u);
    asm("cvt.rn.bf16x2.f32 %0, %1, %2;" : "=r"(l0) : "f"(r1), "f"(r0));
    asm("cvt.rn.bf16x2.f32 %0, %1, %2;" : "=r"(l1) : "f"(r3), "f"(r2));
    hi = make_uint2(h0, h1);
    lo = make_uint2(l0, l1);
}

// ============================ CSR build ============================
__global__ void k_zero() {
    int i = blockIdx.x * blockDim.x + threadIdx.x;
    if (i < NN) { g_deg[i] = 0; g_cursor[i] = 0; }
}
__global__ void k_histo(const int* __restrict__ dst) {
    int e = blockIdx.x * blockDim.x + threadIdx.x;
    if (e < NE) atomicAdd(&g_deg[dst[e]], 1);
}
__global__ void k_scan() {
    __shared__ int s[1024];
    __shared__ int carry_s;
    int tid = threadIdx.x;
    if (tid == 0) carry_s = 0;
    __syncthreads();
    for (int base = 0; base < NN; base += 1024) {
        int i = base + tid;
        int v = (i < NN) ? g_deg[i] : 0;
        if (i < NN) g_dinv[i] = rsqrtf((float)(v + 1));
        s[tid] = v;
        __syncthreads();
#pragma unroll
        for (int off = 1; off < 1024; off <<= 1) {
            int t = (tid >= off) ? s[tid - off] : 0;
            __syncthreads();
            s[tid] += t;
            __syncthreads();
        }
        int incl = s[tid];
        int carry = carry_s;
        if (i < NN) g_rowptr[i] = carry + incl - v;
        __syncthreads();
        if (tid == 1023) carry_s = carry + incl;
        __syncthreads();
    }
    if (tid == 0) g_rowptr[NN] = carry_s;
}
__global__ void k_scatter(const int* __restrict__ src, const int* __restrict__ dst) {
    int e = blockIdx.x * blockDim.x + threadIdx.x;
    if (e < NE) {
        int d = dst[e];
        int p = g_rowptr[d] + atomicAdd(&g_cursor[d], 1);
        g_srcs[p] = src[e];
    }
}

// ============================ HMMA GEMM ============================
// C[i,j] = sum_k A[i,k]*B[j,k]; A:[M,K] fp32 row-major, B:[256,K] fp32 row-major.
// Split: A=Ah+Al, B=Bh+Bl (bf16); acc += AhBh + AhBl + AlBh (fp32).
// CTA: 128(M) x 256(N), 512 threads, 16 warps (4x4), warp tile 32x64.
// EPI 0: C = acc * dinv[row] ; EPI 1: elu(acc+bias) ; EPI 2: acc+bias
#define BM 128
#define BN 256
#define BK 16
#define SROW 48                      // bytes per smem row (16 bf16 + 8 pad)
#define AH_OFF 0
#define AL_OFF (128 * SROW)          // 6144
#define BH_OFF (2 * 128 * SROW)      // 12288
#define BL_OFF (BH_OFF + 256 * SROW) // 24576
#define STG_BYTES (BH_OFF + 2 * 256 * SROW) // 36864
#define SM_TOTAL (2 * STG_BYTES)     // 73728

template <int EPI>
__global__ void __launch_bounds__(512, 1)
k_tgemm(const float* __restrict__ A, const float* __restrict__ B,
        const float* __restrict__ bias, float* __restrict__ C, int M, int K)
{
    extern __shared__ char sm[];
    const uint32_t sb = smem_u32(sm);
    const int tid  = threadIdx.x;
    const int lane = tid & 31;
    const int wid  = tid >> 5;
    const int wm   = wid >> 2;      // 0..3  (M)
    const int wn   = wid & 3;       // 0..3  (N)
    const int bm   = blockIdx.x * BM;

    // fill mapping: each thread loads 4 consecutive k of one row
    const int arow = tid >> 2;          // 0..127
    const int aks  = (tid & 3) * 4;     // k offset 0/4/8/12
    const int brow0 = arow;             // B rows 0..127
    const int brow1 = 128 + arow;       // B rows 128..255

    // ldmatrix lane addresses (byte offsets within a stage)
    const uint32_t a_lrow = (uint32_t)(lane & 15);
    const uint32_t a_lkh  = (uint32_t)((lane >> 4) << 4);        // 0 or 16 bytes
    const uint32_t b_lrow = (uint32_t)((lane & 7) + ((lane >> 4) << 3));
    const uint32_t b_lkh  = (uint32_t)(((lane >> 3) & 1) << 4);

    float acc[2][8][4];
#pragma unroll
    for (int m = 0; m < 2; m++)
#pragma unroll
        for (int n = 0; n < 8; n++)
#pragma unroll
            for (int q = 0; q < 4; q++) acc[m][n][q] = 0.f;

    const int nt = (K + BK - 1) / BK;
    float fa[4], f0[4], f1[4];

    // prefetch stage 0
    {
        const int r = bm + arow;
        const float* Ap = A + (size_t)r * K + aks;
        const float* B0 = B + (size_t)brow0 * K + aks;
        const float* B1 = B + (size_t)brow1 * K + aks;
#pragma unroll
        for (int j = 0; j < 4; j++) {
            int k = aks + j;
            fa[j] = (r < M && k < K) ? __ldg(Ap + j) : 0.f;
            f0[j] = (k < K) ? __ldg(B0 + j) : 0.f;
            f1[j] = (k < K) ? __ldg(B1 + j) : 0.f;
        }
    }

    for (int kt = 0; kt < nt; kt++) {
        const uint32_t stg = (uint32_t)(kt & 1) * STG_BYTES;

        // ---- convert + store prefetched tile ----
        {
            uint2 hi, lo;
            cvt4(fa, hi, lo);
            *(uint2*)(sm + stg + AH_OFF + arow * SROW + (tid & 3) * 8) = hi;
            *(uint2*)(sm + stg + AL_OFF + arow * SROW + (tid & 3) * 8) = lo;
            cvt4(f0, hi, lo);
            *(uint2*)(sm + stg + BH_OFF + brow0 * SROW + (tid & 3) * 8) = hi;
            *(uint2*)(sm + stg + BL_OFF + brow0 * SROW + (tid & 3) * 8) = lo;
            cvt4(f1, hi, lo);
            *(uint2*)(sm + stg + BH_OFF + brow1 * SROW + (tid & 3) * 8) = hi;
            *(uint2*)(sm + stg + BL_OFF + brow1 * SROW + (tid & 3) * 8) = lo;
        }
        __syncthreads();

        // ---- prefetch next stage into registers ----
        if (kt + 1 < nt) {
            const int k0 = (kt + 1) * BK;
            const int r = bm + arow;
            const float* Ap = A + (size_t)r * K + k0 + aks;
            const float* B0 = B + (size_t)brow0 * K + k0 + aks;
            const float* B1 = B + (size_t)brow1 * K + k0 + aks;
#pragma unroll
            for (int j = 0; j < 4; j++) {
                int k = k0 + aks + j;
                fa[j] = (r < M && k < K) ? __ldg(Ap + j) : 0.f;
                f0[j] = (k < K) ? __ldg(B0 + j) : 0.f;
                f1[j] = (k < K) ? __ldg(B1 + j) : 0.f;
            }
        }

        // ---- fragments + MMA ----
        uint32_t ah[2][4], al[2][4];
#pragma unroll
        for (int mt = 0; mt < 2; mt++) {
            uint32_t rowb = (uint32_t)(wm * 32 + mt * 16) + a_lrow;
            ldmx4(ah[mt], sb + stg + AH_OFF + rowb * SROW + a_lkh);
            ldmx4(al[mt], sb + stg + AL_OFF + rowb * SROW + a_lkh);
        }
#pragma unroll
        for (int ng = 0; ng < 4; ng++) {
            uint32_t bh[4], bl[4];
            uint32_t nb = (uint32_t)(wn * 64 + ng * 16) + b_lrow;
            ldmx4(bh, sb + stg + BH_OFF + nb * SROW + b_lkh);
            ldmx4(bl, sb + stg + BL_OFF + nb * SROW + b_lkh);
#pragma unroll
            for (int mt = 0; mt < 2; mt++) {
#pragma unroll
                for (int nf = 0; nf < 2; nf++) {
                    float* c = acc[mt][ng * 2 + nf];
                    mma_bf16(c, ah[mt], &bh[nf * 2]);
                    mma_bf16(c, ah[mt], &bl[nf * 2]);
                    mma_bf16(c, al[mt], &bh[nf * 2]);
                }
            }
        }
        // next iter stores into the other buffer; the syncthreads above
        // guarantees no warp is still reading it (see pipeline argument).
    }

    // ---- epilogue ----
#pragma unroll
    for (int mt = 0; mt < 2; mt++) {
        int r0 = bm + wm * 32 + mt * 16 + (lane >> 2);
        int r1 = r0 + 8;
        float dv0 = 0.f, dv1 = 0.f;
        if (EPI == 0) {
            if (r0 < M) dv0 = g_dinv[r0];
            if (r1 < M) dv1 = g_dinv[r1];
        }
#pragma unroll
        for (int n = 0; n < 8; n++) {
            int col = wn * 64 + n * 8 + (lane & 3) * 2;
            float b0 = 0.f, b1 = 0.f;
            if (EPI != 0) { b0 = __ldg(bias + col); b1 = __ldg(bias + col + 1); }
            float* c = acc[mt][n];
            float v0 = c[0], v1 = c[1], v2 = c[2], v3 = c[3];
            if (EPI == 0) { v0 *= dv0; v1 *= dv0; v2 *= dv1; v3 *= dv1; }
            else {
                v0 += b0; v1 += b1; v2 += b0; v3 += b1;
                if (EPI == 1) {
                    v0 = (v0 > 0.f) ? v0 : expm1f(v0);
                    v1 = (v1 > 0.f) ? v1 : expm1f(v1);
                    v2 = (v2 > 0.f) ? v2 : expm1f(v2);
                    v3 = (v3 > 0.f) ? v3 : expm1f(v3);
                }
            }
            if (r0 < M) *(float2*)(C + (size_t)r0 * BN + col) = make_float2(v0, v1);
            if (r1 < M) *(float2*)(C + (size_t)r1 * BN + col) = make_float2(v2, v3);
        }
    }
}

// ============================ aggregation ============================
// out[v] = l2norm( relu( dinv[v]*(sum_{u->v} hs[u] + hs[v]) + bias ) )
__global__ void __launch_bounds__(HD)
k_agg(const float* __restrict__ hs, const float* __restrict__ bias,
      float* __restrict__ outx)
{
    int v = blockIdx.x;
    int j = threadIdx.x;

    float s = hs[(size_t)v * HD + j];
    int beg = g_rowptr[v], end = g_rowptr[v + 1];
    for (int e = beg; e < end; e++) {
        int u = g_srcs[e];
        s += hs[(size_t)u * HD + j];
    }
    float val = fmaf(g_dinv[v], s, bias[j]);
    val = fmaxf(val, 0.f);

    __shared__ float red[8];
    float ss = val * val;
#pragma unroll
    for (int o = 16; o; o >>= 1) ss += __shfl_xor_sync(0xffffffffu, ss, o);
    if ((j & 31) == 0) red[j >> 5] = ss;
    __syncthreads();
    if (j < 8) {
        float t = red[j];
#pragma unroll
        for (int o = 4; o; o >>= 1) t += __shfl_xor_sync(0xffu, t, o);
        if (j == 0) red[0] = t;
    }
    __syncthreads();
    float scale = 1.f / fmaxf(sqrtf(red[0]), 1e-12f);
    outx[(size_t)v * HD + j] = val * scale;
}

// ============================ launch ============================
extern "C" void kernel_launch(void* const* d_in, const int* in_sizes, int n_in,
                              void* d_out, int out_size)
{
    const float* x     = (const float*)d_in[0];
    const int*   edges = (const int*)  d_in[1];
    const float* Wg0   = (const float*)d_in[2];
    const float* bg0   = (const float*)d_in[3];
    const float* Wg1   = (const float*)d_in[4];
    const float* bg1   = (const float*)d_in[5];
    const float* Wg2   = (const float*)d_in[6];
    const float* bg2   = (const float*)d_in[7];
    const float* W1    = (const float*)d_in[8];
    const float* b1    = (const float*)d_in[9];
    const float* W2    = (const float*)d_in[10];
    const float* b2    = (const float*)d_in[11];
    float* out = (float*)d_out;

    const int* src = edges;
    const int* dst = edges + NE;

    float *hp, *xp;
    cudaGetSymbolAddress((void**)&hp, g_h);
    cudaGetSymbolAddress((void**)&xp, g_x);

    cudaFuncSetAttribute(k_tgemm<0>, cudaFuncAttributeMaxDynamicSharedMemorySize, SM_TOTAL);
    cudaFuncSetAttribute(k_tgemm<1>, cudaFuncAttributeMaxDynamicSharedMemorySize, SM_TOTAL);
    cudaFuncSetAttribute(k_tgemm<2>, cudaFuncAttributeMaxDynamicSharedMemorySize, SM_TOTAL);

    // CSR build + dinv
    k_zero   <<<(NN + 255) / 256, 256>>>();
    k_histo  <<<(NE + 255) / 256, 256>>>(dst);
    k_scan   <<<1, 1024>>>();
    k_scatter<<<(NE + 255) / 256, 256>>>(src, dst);

    const int grd = (NN + BM - 1) / BM;   // 391

    // GCN layer 0 (K = 2613)
    k_tgemm<0><<<grd, 512, SM_TOTAL>>>(x,  Wg0, nullptr, hp, NN, IND);
    k_agg     <<<NN, HD>>>(hp, bg0, xp);
    // GCN layer 1
    k_tgemm<0><<<grd, 512, SM_TOTAL>>>(xp, Wg1, nullptr, hp, NN, HD);
    k_agg     <<<NN, HD>>>(hp, bg1, xp);
    // GCN layer 2
    k_tgemm<0><<<grd, 512, SM_TOTAL>>>(xp, Wg2, nullptr, hp, NN, HD);
    k_agg     <<<NN, HD>>>(hp, bg2, xp);
    // MLP
    k_tgemm<1><<<grd, 512, SM_TOTAL>>>(xp, W1, b1, hp,  NN, HD);
    k_tgemm<2><<<grd, 512, SM_TOTAL>>>(hp, W2, b2, out, NN, HD);
}